// round 10
// baseline (speedup 1.0000x reference)
#include <cuda_runtime.h>
#include <cuda_fp16.h>
#include <cstdint>

// Problem dims (fixed by the reference)
#define BB 16
#define TT 2048
#define DD 1024
#define HH 1024
#define MM (BB*TT)      // 32768 rows
#define N3 (3*HH)       // 3072 GEMM output cols: [x_tilde | g(2048)]

// ---------------- scratch (allocation-free __device__ globals) ----------------
__device__ __half  g_Xh[(size_t)MM * DD];       //  64 MB  fp16 X
__device__ __half  g_Wh[(size_t)N3 * DD];       //   6 MB  fp16 [Wlt; Wg]
__device__ __half  g_Yh[(size_t)MM * N3];       // 201 MB  GEMM output, fp16
__device__ float4  g_fnd[(size_t)MM * HH / 2];  // 268 MB  per row m: float2[h]=(f,nd)
__device__ float4  g_r4[(size_t)MM * HH / 4];   // 134 MB  r gate
__device__ float4  g_c4[(size_t)MM * HH / 4];   // 134 MB  all_c

// ---------------- helpers ----------------
__device__ __forceinline__ uint32_t smem_u32(const void* p) {
    return (uint32_t)__cvta_generic_to_shared(p);
}
#define CP_ASYNC16(dst, src) \
    asm volatile("cp.async.cg.shared.global [%0], [%1], 16;" :: "r"(dst), "l"(src))
#define CP_COMMIT() asm volatile("cp.async.commit_group;" ::: "memory")

#define LDSM_X4(r0, r1, r2, r3, addr) \
    asm volatile("ldmatrix.sync.aligned.m8n8.x4.shared.b16 {%0,%1,%2,%3}, [%4];" \
        : "=r"(r0), "=r"(r1), "=r"(r2), "=r"(r3) : "r"(addr))

__device__ __forceinline__ void mma_f16(float* d, const uint32_t* a, const uint32_t* b) {
    asm volatile(
        "mma.sync.aligned.m16n8k16.row.col.f32.f16.f16.f32 "
        "{%0,%1,%2,%3}, {%4,%5,%6,%7}, {%8,%9}, {%0,%1,%2,%3};"
        : "+f"(d[0]), "+f"(d[1]), "+f"(d[2]), "+f"(d[3])
        : "r"(a[0]), "r"(a[1]), "r"(a[2]), "r"(a[3]),
          "r"(b[0]), "r"(b[1]));
}

__device__ __forceinline__ float sigmoidf_(float z) {
    return 1.0f / (1.0f + __expf(-z));
}

// block reduce (sum, sumsq) for 256-thread blocks (8 warps)
__device__ __forceinline__ void block_reduce2(float& s, float& q, float* sh) {
    #pragma unroll
    for (int o = 16; o; o >>= 1) {
        s += __shfl_xor_sync(0xFFFFFFFFu, s, o);
        q += __shfl_xor_sync(0xFFFFFFFFu, q, o);
    }
    int warp = threadIdx.x >> 5, lane = threadIdx.x & 31;
    if (lane == 0) { sh[warp] = s; sh[8 + warp] = q; }
    __syncthreads();
    if (threadIdx.x < 32) {
        float ss = (lane < 8) ? sh[lane] : 0.0f;
        float qq = (lane < 8) ? sh[8 + lane] : 0.0f;
        #pragma unroll
        for (int o = 4; o; o >>= 1) {
            ss += __shfl_xor_sync(0xFFFFFFFFu, ss, o);
            qq += __shfl_xor_sync(0xFFFFFFFFu, qq, o);
        }
        if (lane == 0) { sh[0] = ss; sh[8] = qq; }
    }
    __syncthreads();
    s = sh[0]; q = sh[8];
}

// ---------------- K0: fp32 -> fp16 conversion ----------------
__global__ __launch_bounds__(256)
void cvt_kernel(const float* __restrict__ src, __half* __restrict__ dst, int n4) {
    int i = blockIdx.x * 256 + threadIdx.x;
    if (i < n4) {
        float4 v = ((const float4*)src)[i];
        __half2* d = (__half2*)dst;
        d[2 * i]     = __floats2half2_rn(v.x, v.y);
        d[2 * i + 1] = __floats2half2_rn(v.z, v.w);
    }
}

// ---------------- K1: fp16 mma.sync GEMM  Y[m,n] = sum_d x[m,d] * W[n,d] ----------------
// CTA tile 128x128, 4 warps as 2x2 (warp tile 64x64), K-chunk 64, 3-stage cp.async.
// ldmatrix.x4 + register double-buffered fragments; 2 CTAs/SM.
#define TMh 128
#define TNh 128
#define KCh 64
#define LDKH 72                          // halfs per smem row (144B, conflict-free)
#define A_STH (TMh * LDKH)               // 9216 halfs
#define B_STH (TNh * LDKH)               // 9216 halfs
#define STAGE_H (A_STH + B_STH)          // 18432 halfs = 36864 B
#define SMEM_GEMM_BYTES (3 * STAGE_H * 2)   // 110592
#define NTHR 128

// fill one stage with K-chunk kt: A 8 chunks/thread, B 8 chunks/thread (16B each)
__device__ __forceinline__ void load_stage(__half* stg, const __half* Xrow,
                                           const __half* Wrow, int kt, int tid) {
    const int kof = kt * KCh;
    const uint32_t aB = smem_u32(stg);
    const uint32_t bB = smem_u32(stg + A_STH);
    #pragma unroll
    for (int j = 0; j < 8; j++) {
        int c = tid + j * NTHR;          // 0..1023 = row*8 + q
        int row = c >> 3, q = c & 7;
        CP_ASYNC16(aB + (uint32_t)(row * 144 + q * 16),
                   Xrow + (size_t)row * DD + kof + q * 8);
    }
    #pragma unroll
    for (int j = 0; j < 8; j++) {
        int c = tid + j * NTHR;
        int row = c >> 3, q = c & 7;
        CP_ASYNC16(bB + (uint32_t)(row * 144 + q * 16),
                   Wrow + (size_t)row * DD + kof + q * 8);
    }
    CP_COMMIT();
}

__global__ __launch_bounds__(NTHR, 2)
void gemm_f16(void) {
    extern __shared__ __half sh[];
    const int tid = threadIdx.x;
    const int lane = tid & 31, warp = tid >> 5;
    const int qr = lane >> 2, qc = lane & 3;
    const int wm = (warp >> 1) * 64, wn = (warp & 1) * 64;

    const int m_cta = blockIdx.y * TMh;
    const int n_cta = blockIdx.x * TNh;
    const __half* Xrow = g_Xh + (size_t)m_cta * DD;
    const __half* Wrow = g_Wh + (size_t)n_cta * DD;

    // ldmatrix byte offsets (relative to stage A / stage B bases)
    // A (mi-th 16x16 tile): row = lane%16, col = (lane/16)*8
    uint32_t aoff[4];
    {
        int row = lane & 15, col = (lane >> 4) * 8;
        #pragma unroll
        for (int mi = 0; mi < 4; mi++)
            aoff[mi] = (uint32_t)(((wm + mi * 16 + row) * LDKH + col) * 2);
    }
    // B (p-th pair of 8-row n tiles, p=0..3): row = wn + p*16 + (subm>>1)*8 + (lane&7),
    //                                          col = (subm&1)*8,  subm = lane>>3
    uint32_t boff[4];
    {
        int subm = lane >> 3, within = lane & 7;
        int rb = (subm >> 1) * 8 + within, cb = (subm & 1) * 8;
        #pragma unroll
        for (int p = 0; p < 4; p++)
            boff[p] = (uint32_t)(((wn + p * 16 + rb) * LDKH + cb) * 2);
    }
    const uint32_t smem_base = smem_u32(sh);

    float acc[4][8][4];
    #pragma unroll
    for (int mi = 0; mi < 4; mi++)
        #pragma unroll
        for (int ni = 0; ni < 8; ni++)
            #pragma unroll
            for (int k = 0; k < 4; k++) acc[mi][ni][k] = 0.0f;

    // prologue: stages 0,1 <- chunks 0,1
    load_stage(sh, Xrow, Wrow, 0, tid);
    load_stage(sh + STAGE_H, Xrow, Wrow, 1, tid);

    uint32_t a[2][4][4], b[2][8][2];

    const int KT = DD / KCh;   // 16
    int stage = 0;
    for (int kt = 0; kt < KT; kt++) {
        if (kt < 15) { asm volatile("cp.async.wait_group 1;" ::: "memory"); }
        else         { asm volatile("cp.async.wait_group 0;" ::: "memory"); }
        __syncthreads();   // chunk kt visible; everyone done computing kt-1

        // prefetch chunk kt+2 into the stage freed by chunk kt-1
        if (kt + 2 < KT) {
            int ps = stage + 2; if (ps >= 3) ps -= 3;
            load_stage(sh + ps * STAGE_H, Xrow, Wrow, kt + 2, tid);
        }

        const uint32_t stA = smem_base + (uint32_t)(stage * STAGE_H * 2);
        const uint32_t stB = stA + A_STH * 2;

        // load kk=0 fragments
        #pragma unroll
        for (int mi = 0; mi < 4; mi++)
            LDSM_X4(a[0][mi][0], a[0][mi][1], a[0][mi][2], a[0][mi][3],
                    stA + aoff[mi]);
        #pragma unroll
        for (int p = 0; p < 4; p++)
            LDSM_X4(b[0][2*p][0], b[0][2*p][1], b[0][2*p+1][0], b[0][2*p+1][1],
                    stB + boff[p]);

        #pragma unroll
        for (int kk = 0; kk < 4; kk++) {
            const int cur = kk & 1, nxt = cur ^ 1;
            if (kk < 3) {   // prefetch kk+1 fragments before the HMMA burst
                #pragma unroll
                for (int mi = 0; mi < 4; mi++)
                    LDSM_X4(a[nxt][mi][0], a[nxt][mi][1], a[nxt][mi][2], a[nxt][mi][3],
                            stA + aoff[mi] + (kk + 1) * 32);
                #pragma unroll
                for (int p = 0; p < 4; p++)
                    LDSM_X4(b[nxt][2*p][0], b[nxt][2*p][1],
                            b[nxt][2*p+1][0], b[nxt][2*p+1][1],
                            stB + boff[p] + (kk + 1) * 32);
            }
            #pragma unroll
            for (int mi = 0; mi < 4; mi++)
                #pragma unroll
                for (int ni = 0; ni < 8; ni++)
                    mma_f16(acc[mi][ni], a[cur][mi], b[cur][ni]);
        }
        if (++stage == 3) stage = 0;
    }

    // epilogue: fp16 stores (rows qr / qr+8, cols 2qc,2qc+1)
    __half* Y = g_Yh;
    #pragma unroll
    for (int mi = 0; mi < 4; mi++) {
        #pragma unroll
        for (int ni = 0; ni < 8; ni++) {
            int r = m_cta + wm + mi * 16 + qr;
            int col = n_cta + wn + ni * 8 + qc * 2;
            *(__half2*)&Y[(size_t)r * N3 + col] =
                __floats2half2_rn(acc[mi][ni][0], acc[mi][ni][1]);
            *(__half2*)&Y[(size_t)(r + 8) * N3 + col] =
                __floats2half2_rn(acc[mi][ni][2], acc[mi][ni][3]);
        }
    }
}

// ---------------- K2: gate = sigmoid(LN(g + b_g)); emit (f,(1-f)*xt) and r ----------------
__global__ __launch_bounds__(256)
void gate_kernel(const float* __restrict__ bg, const float* __restrict__ gg,
                 const float* __restrict__ betg) {
    __shared__ float sh[16];
    const int m = blockIdx.x;
    const int tid = threadIdx.x;
    const __half* Yrow = g_Yh + (size_t)m * N3;

    // g half: 8 values per thread (4*tid..4*tid+3 and +1024)
    const __half2* G = (const __half2*)(Yrow + HH);
    __half2 ga0 = G[2 * tid], ga1 = G[2 * tid + 1];
    __half2 gb0 = G[512 + 2 * tid], gb1 = G[512 + 2 * tid + 1];
    float4 b0 = ((const float4*)bg)[tid];
    float4 b1 = ((const float4*)bg)[256 + tid];
    float4 v0, v1;
    v0.x = __low2float(ga0) + b0.x;  v0.y = __high2float(ga0) + b0.y;
    v0.z = __low2float(ga1) + b0.z;  v0.w = __high2float(ga1) + b0.w;
    v1.x = __low2float(gb0) + b1.x;  v1.y = __high2float(gb0) + b1.y;
    v1.z = __low2float(gb1) + b1.z;  v1.w = __high2float(gb1) + b1.w;

    float s = v0.x + v0.y + v0.z + v0.w + v1.x + v1.y + v1.z + v1.w;
    float q = v0.x*v0.x + v0.y*v0.y + v0.z*v0.z + v0.w*v0.w
            + v1.x*v1.x + v1.y*v1.y + v1.z*v1.z + v1.w*v1.w;
    block_reduce2(s, q, sh);
    const float mu = s * (1.0f / 2048.0f);
    const float var = q * (1.0f / 2048.0f) - mu * mu;
    const float rs = rsqrtf(var + 1e-5f);

    // f half: j = 4*tid .. 4*tid+3
    float4 gg0 = ((const float4*)gg)[tid];
    float4 bt0 = ((const float4*)betg)[tid];
    const __half2* XT = (const __half2*)Yrow;
    __half2 xt0 = XT[2 * tid], xt1 = XT[2 * tid + 1];
    float f0 = sigmoidf_((v0.x - mu) * rs * gg0.x + bt0.x);
    float f1 = sigmoidf_((v0.y - mu) * rs * gg0.y + bt0.y);
    float f2 = sigmoidf_((v0.z - mu) * rs * gg0.z + bt0.z);
    float f3 = sigmoidf_((v0.w - mu) * rs * gg0.w + bt0.w);
    float4* fd = g_fnd + (size_t)m * 512 + 2 * tid;
    fd[0] = make_float4(f0, (1.0f - f0) * __low2float(xt0),
                        f1, (1.0f - f1) * __high2float(xt0));
    fd[1] = make_float4(f2, (1.0f - f2) * __low2float(xt1),
                        f3, (1.0f - f3) * __high2float(xt1));

    // r half: jg = 1024 + 4*tid ..
    float4 gg1 = ((const float4*)gg)[256 + tid];
    float4 bt1 = ((const float4*)betg)[256 + tid];
    float4 rv;
    rv.x = sigmoidf_((v1.x - mu) * rs * gg1.x + bt1.x);
    rv.y = sigmoidf_((v1.y - mu) * rs * gg1.y + bt1.y);
    rv.z = sigmoidf_((v1.z - mu) * rs * gg1.z + bt1.z);
    rv.w = sigmoidf_((v1.w - mu) * rs * gg1.w + bt1.w);
    g_r4[(size_t)m * 256 + tid] = rv;
}

// ---------------- K3: sequential scan over T; explicit double-buffered prefetch ----------------
#define SCAN_U 8
__global__ __launch_bounds__(64)
void scan_kernel(const float* __restrict__ c0, float* __restrict__ cfinal) {
    const int ch = blockIdx.x * 64 + threadIdx.x;   // 0..16383
    const int b = ch >> 10, h = ch & 1023;
    float c = c0[ch];
    const float2* src = (const float2*)g_fnd;       // (f, nd) at (b*TT + t)*1024 + h
    float* dst = (float*)g_c4;
    const size_t base = (size_t)b * TT * 1024 + h;

    float2 buf[SCAN_U];
    #pragma unroll
    for (int j = 0; j < SCAN_U; j++) buf[j] = src[base + (size_t)j * 1024];

    for (int t0 = 0; t0 < TT; t0 += SCAN_U) {
        float2 cur[SCAN_U];
        #pragma unroll
        for (int j = 0; j < SCAN_U; j++) cur[j] = buf[j];
        if (t0 + SCAN_U < TT) {
            #pragma unroll
            for (int j = 0; j < SCAN_U; j++)
                buf[j] = src[base + (size_t)(t0 + SCAN_U + j) * 1024];
        }
        #pragma unroll
        for (int j = 0; j < SCAN_U; j++) {
            c = fmaf(cur[j].x, c, cur[j].y);
            dst[base + (size_t)(t0 + j) * 1024] = c;
        }
    }
    cfinal[ch] = c;
}

// ---------------- K4: h = r * sigmoid(LN(all_c)) + (1-r) * x ----------------
__global__ __launch_bounds__(256)
void out_kernel(const float* __restrict__ x, const float* __restrict__ ga,
                const float* __restrict__ ba, float* __restrict__ hout) {
    __shared__ float sh[16];
    const int m = blockIdx.x;
    const int tid = threadIdx.x;

    float4 cv = g_c4[(size_t)m * 256 + tid];
    float s = cv.x + cv.y + cv.z + cv.w;
    float q = cv.x*cv.x + cv.y*cv.y + cv.z*cv.z + cv.w*cv.w;
    block_reduce2(s, q, sh);
    const float mu = s * (1.0f / 1024.0f);
    const float var = q * (1.0f / 1024.0f) - mu * mu;
    const float rs = rsqrtf(var + 1e-5f);

    float4 gv = ((const float4*)ga)[tid];
    float4 bv = ((const float4*)ba)[tid];
    float4 rv = g_r4[(size_t)m * 256 + tid];
    float4 xv = ((const float4*)(x + (size_t)m * HH))[tid];
    float4 h;
    h.x = rv.x * sigmoidf_((cv.x - mu) * rs * gv.x + bv.x) + (1.0f - rv.x) * xv.x;
    h.y = rv.y * sigmoidf_((cv.y - mu) * rs * gv.y + bv.y) + (1.0f - rv.y) * xv.y;
    h.z = rv.z * sigmoidf_((cv.z - mu) * rs * gv.z + bv.z) + (1.0f - rv.z) * xv.z;
    h.w = rv.w * sigmoidf_((cv.w - mu) * rs * gv.w + bv.w) + (1.0f - rv.w) * xv.w;
    ((float4*)(hout + (size_t)m * HH))[tid] = h;
}

// ---------------- launch ----------------
extern "C" void kernel_launch(void* const* d_in, const int* in_sizes, int n_in,
                              void* d_out, int out_size) {
    const float* x    = (const float*)d_in[0];
    const float* c    = (const float*)d_in[1];
    const float* Wlt  = (const float*)d_in[2];
    const float* Wg   = (const float*)d_in[3];
    const float* bg   = (const float*)d_in[4];
    const float* gg   = (const float*)d_in[5];
    const float* betg = (const float*)d_in[6];
    const float* ga   = (const float*)d_in[7];
    const float* ba   = (const float*)d_in[8];
    float* out = (float*)d_out;

    __half* dXh; cudaGetSymbolAddress((void**)&dXh, g_Xh);
    __half* dWh; cudaGetSymbolAddress((void**)&dWh, g_Wh);

    // fp32 -> fp16 conversions
    cvt_kernel<<<(MM * DD / 4 + 255) / 256, 256>>>(x, dXh, MM * DD / 4);
    cvt_kernel<<<(HH * DD / 4 + 255) / 256, 256>>>(Wlt, dWh, HH * DD / 4);
    cvt_kernel<<<(2 * HH * DD / 4 + 255) / 256, 256>>>(Wg, dWh + (size_t)HH * DD,
                                                       2 * HH * DD / 4);

    cudaFuncSetAttribute(gemm_f16, cudaFuncAttributeMaxDynamicSharedMemorySize,
                         SMEM_GEMM_BYTES);
    dim3 grid(N3 / TNh, MM / TMh);   // (24, 256), x-major for L2 reuse of X strips
    gemm_f16<<<grid, NTHR, SMEM_GEMM_BYTES>>>();

    gate_kernel<<<MM, 256>>>(bg, gg, betg);
    scan_kernel<<<256, 64>>>(c, out + (size_t)MM * HH);
    out_kernel<<<MM, 256>>>(x, ga, ba, out);
}

// round 11
// speedup vs baseline: 1.0457x; 1.0457x over previous
#include <cuda_runtime.h>
#include <cuda_fp16.h>
#include <cstdint>

// Problem dims (fixed by the reference)
#define BB 16
#define TT 2048
#define DD 1024
#define HH 1024
#define MM (BB*TT)      // 32768 rows
#define N3 (3*HH)       // 3072 GEMM output cols: [x_tilde | g(2048)]

// ---------------- scratch (allocation-free __device__ globals) ----------------
__device__ __half  g_Xh[(size_t)MM * DD];       //  64 MB  fp16 X
__device__ __half  g_Wh[(size_t)N3 * DD];       //   6 MB  fp16 [Wlt; Wg]
__device__ __half  g_Yh[(size_t)MM * N3];       // 201 MB  GEMM output, fp16
__device__ __half2 g_fndh[(size_t)MM * HH];     // 134 MB  (f, nd) per (m,h), fp16
__device__ __half  g_rh[(size_t)MM * HH];       //  67 MB  r gate, fp16
__device__ float4  g_c4[(size_t)MM * HH / 4];   // 134 MB  all_c (fp32: LN-sensitive)

// ---------------- helpers ----------------
__device__ __forceinline__ uint32_t smem_u32(const void* p) {
    return (uint32_t)__cvta_generic_to_shared(p);
}
#define CP_ASYNC16(dst, src) \
    asm volatile("cp.async.cg.shared.global [%0], [%1], 16;" :: "r"(dst), "l"(src))
#define CP_COMMIT() asm volatile("cp.async.commit_group;" ::: "memory")

#define LDSM_X4(r0, r1, r2, r3, addr) \
    asm volatile("ldmatrix.sync.aligned.m8n8.x4.shared.b16 {%0,%1,%2,%3}, [%4];" \
        : "=r"(r0), "=r"(r1), "=r"(r2), "=r"(r3) : "r"(addr))

__device__ __forceinline__ void mma_f16(float* d, const uint32_t* a, const uint32_t* b) {
    asm volatile(
        "mma.sync.aligned.m16n8k16.row.col.f32.f16.f16.f32 "
        "{%0,%1,%2,%3}, {%4,%5,%6,%7}, {%8,%9}, {%0,%1,%2,%3};"
        : "+f"(d[0]), "+f"(d[1]), "+f"(d[2]), "+f"(d[3])
        : "r"(a[0]), "r"(a[1]), "r"(a[2]), "r"(a[3]),
          "r"(b[0]), "r"(b[1]));
}

__device__ __forceinline__ float sigmoidf_(float z) {
    return 1.0f / (1.0f + __expf(-z));
}

// block reduce (sum, sumsq) for 256-thread blocks (8 warps)
__device__ __forceinline__ void block_reduce2(float& s, float& q, float* sh) {
    #pragma unroll
    for (int o = 16; o; o >>= 1) {
        s += __shfl_xor_sync(0xFFFFFFFFu, s, o);
        q += __shfl_xor_sync(0xFFFFFFFFu, q, o);
    }
    int warp = threadIdx.x >> 5, lane = threadIdx.x & 31;
    if (lane == 0) { sh[warp] = s; sh[8 + warp] = q; }
    __syncthreads();
    if (threadIdx.x < 32) {
        float ss = (lane < 8) ? sh[lane] : 0.0f;
        float qq = (lane < 8) ? sh[8 + lane] : 0.0f;
        #pragma unroll
        for (int o = 4; o; o >>= 1) {
            ss += __shfl_xor_sync(0xFFFFFFFFu, ss, o);
            qq += __shfl_xor_sync(0xFFFFFFFFu, qq, o);
        }
        if (lane == 0) { sh[0] = ss; sh[8] = qq; }
    }
    __syncthreads();
    s = sh[0]; q = sh[8];
}

// ---------------- K0: fp32 -> fp16 conversion ----------------
__global__ __launch_bounds__(256)
void cvt_kernel(const float* __restrict__ src, __half* __restrict__ dst, int n4) {
    int i = blockIdx.x * 256 + threadIdx.x;
    if (i < n4) {
        float4 v = ((const float4*)src)[i];
        __half2* d = (__half2*)dst;
        d[2 * i]     = __floats2half2_rn(v.x, v.y);
        d[2 * i + 1] = __floats2half2_rn(v.z, v.w);
    }
}

// ---------------- K1: fp16 mma.sync GEMM  Y[m,n] = sum_d x[m,d] * W[n,d] ----------------
// CTA tile 128x128, warp tile 64x32 (8 warps as 2x4), K-chunk 64, 3-stage cp.async.
// ldmatrix.x4 fragment feeding; 2 CTAs/SM; one barrier per 64 HMMAs.  (R9 config)
#define TMh 128
#define TNh 128
#define KCh 64
#define LDKH 72                          // halfs per smem row (144B, conflict-free)
#define A_STH (TMh * LDKH)               // 9216 halfs
#define B_STH (TNh * LDKH)               // 9216 halfs
#define STAGE_H (A_STH + B_STH)          // 18432 halfs = 36864 B
#define SMEM_GEMM_BYTES (3 * STAGE_H * 2)   // 110592

// fill one stage with K-chunk kt: A 4 chunks/thread, B 4 chunks/thread (16B each)
__device__ __forceinline__ void load_stage(__half* stg, const __half* Xrow,
                                           const __half* Wrow, int kt, int tid) {
    const int kof = kt * KCh;
    const uint32_t aB = smem_u32(stg);
    const uint32_t bB = smem_u32(stg + A_STH);
    #pragma unroll
    for (int j = 0; j < 4; j++) {
        int c = tid + j * 256;           // 0..1023 = row*8 + q
        int row = c >> 3, q = c & 7;
        CP_ASYNC16(aB + (uint32_t)(row * 144 + q * 16),
                   Xrow + (size_t)row * DD + kof + q * 8);
    }
    #pragma unroll
    for (int j = 0; j < 4; j++) {
        int c = tid + j * 256;
        int row = c >> 3, q = c & 7;
        CP_ASYNC16(bB + (uint32_t)(row * 144 + q * 16),
                   Wrow + (size_t)row * DD + kof + q * 8);
    }
    CP_COMMIT();
}

__global__ __launch_bounds__(256, 2)
void gemm_f16(void) {
    extern __shared__ __half sh[];
    const int tid = threadIdx.x;
    const int lane = tid & 31, warp = tid >> 5;
    const int qr = lane >> 2, qc = lane & 3;
    const int wm = (warp >> 2) * 64, wn = (warp & 3) * 32;

    const int m_cta = blockIdx.y * TMh;
    const int n_cta = blockIdx.x * TNh;
    const __half* Xrow = g_Xh + (size_t)m_cta * DD;
    const __half* Wrow = g_Wh + (size_t)n_cta * DD;

    // ldmatrix byte offsets (relative to stage A / stage B bases)
    uint32_t aoff[4];
    {
        int row = lane & 15, col = (lane >> 4) * 8;
        #pragma unroll
        for (int mi = 0; mi < 4; mi++)
            aoff[mi] = (uint32_t)(((wm + mi * 16 + row) * LDKH + col) * 2);
    }
    uint32_t boff[2];
    {
        int subm = lane >> 3, within = lane & 7;
        int rb = (subm >> 1) * 8 + within, cb = (subm & 1) * 8;
        #pragma unroll
        for (int p = 0; p < 2; p++)
            boff[p] = (uint32_t)(((wn + p * 16 + rb) * LDKH + cb) * 2);
    }
    const uint32_t smem_base = smem_u32(sh);

    float acc[4][4][4];
    #pragma unroll
    for (int mi = 0; mi < 4; mi++)
        #pragma unroll
        for (int ni = 0; ni < 4; ni++)
            #pragma unroll
            for (int k = 0; k < 4; k++) acc[mi][ni][k] = 0.0f;

    // prologue: stages 0,1 <- chunks 0,1
    load_stage(sh, Xrow, Wrow, 0, tid);
    load_stage(sh + STAGE_H, Xrow, Wrow, 1, tid);

    const int KT = DD / KCh;   // 16
    int stage = 0;
    for (int kt = 0; kt < KT; kt++) {
        if (kt < 15) { asm volatile("cp.async.wait_group 1;" ::: "memory"); }
        else         { asm volatile("cp.async.wait_group 0;" ::: "memory"); }
        __syncthreads();   // chunk kt visible; everyone done computing kt-1

        if (kt + 2 < KT) {
            int ps = stage + 2; if (ps >= 3) ps -= 3;
            load_stage(sh + ps * STAGE_H, Xrow, Wrow, kt + 2, tid);
        }

        const uint32_t stA = smem_base + (uint32_t)(stage * STAGE_H * 2);
        const uint32_t stB = stA + A_STH * 2;

        #pragma unroll
        for (int kk = 0; kk < 4; kk++) {
            uint32_t a[4][4], b[4][2];
            #pragma unroll
            for (int mi = 0; mi < 4; mi++)
                LDSM_X4(a[mi][0], a[mi][1], a[mi][2], a[mi][3],
                        stA + aoff[mi] + kk * 32);
            #pragma unroll
            for (int p = 0; p < 2; p++)
                LDSM_X4(b[2*p][0], b[2*p][1], b[2*p+1][0], b[2*p+1][1],
                        stB + boff[p] + kk * 32);
            #pragma unroll
            for (int mi = 0; mi < 4; mi++)
                #pragma unroll
                for (int ni = 0; ni < 4; ni++)
                    mma_f16(acc[mi][ni], a[mi], b[ni]);
        }
        if (++stage == 3) stage = 0;
    }

    // epilogue: fp16 stores (rows qr / qr+8, cols 2qc,2qc+1)
    __half* Y = g_Yh;
    #pragma unroll
    for (int mi = 0; mi < 4; mi++) {
        #pragma unroll
        for (int ni = 0; ni < 4; ni++) {
            int r = m_cta + wm + mi * 16 + qr;
            int col = n_cta + wn + ni * 8 + qc * 2;
            *(__half2*)&Y[(size_t)r * N3 + col] =
                __floats2half2_rn(acc[mi][ni][0], acc[mi][ni][1]);
            *(__half2*)&Y[(size_t)(r + 8) * N3 + col] =
                __floats2half2_rn(acc[mi][ni][2], acc[mi][ni][3]);
        }
    }
}

// ---------------- K2: gate = sigmoid(LN(g + b_g)); emit (f,nd) half2 and r half ----------------
__global__ __launch_bounds__(256)
void gate_kernel(const float* __restrict__ bg, const float* __restrict__ gg,
                 const float* __restrict__ betg) {
    __shared__ float sh[16];
    const int m = blockIdx.x;
    const int tid = threadIdx.x;
    const __half* Yrow = g_Yh + (size_t)m * N3;

    // g half: 8 values per thread (4*tid..4*tid+3 and +1024)
    const __half2* G = (const __half2*)(Yrow + HH);
    __half2 ga0 = G[2 * tid], ga1 = G[2 * tid + 1];
    __half2 gb0 = G[512 + 2 * tid], gb1 = G[512 + 2 * tid + 1];
    float4 b0 = ((const float4*)bg)[tid];
    float4 b1 = ((const float4*)bg)[256 + tid];
    float4 v0, v1;
    v0.x = __low2float(ga0) + b0.x;  v0.y = __high2float(ga0) + b0.y;
    v0.z = __low2float(ga1) + b0.z;  v0.w = __high2float(ga1) + b0.w;
    v1.x = __low2float(gb0) + b1.x;  v1.y = __high2float(gb0) + b1.y;
    v1.z = __low2float(gb1) + b1.z;  v1.w = __high2float(gb1) + b1.w;

    float s = v0.x + v0.y + v0.z + v0.w + v1.x + v1.y + v1.z + v1.w;
    float q = v0.x*v0.x + v0.y*v0.y + v0.z*v0.z + v0.w*v0.w
            + v1.x*v1.x + v1.y*v1.y + v1.z*v1.z + v1.w*v1.w;
    block_reduce2(s, q, sh);
    const float mu = s * (1.0f / 2048.0f);
    const float var = q * (1.0f / 2048.0f) - mu * mu;
    const float rs = rsqrtf(var + 1e-5f);

    // f half: j = 4*tid .. 4*tid+3
    float4 gg0 = ((const float4*)gg)[tid];
    float4 bt0 = ((const float4*)betg)[tid];
    const __half2* XT = (const __half2*)Yrow;
    __half2 xt0 = XT[2 * tid], xt1 = XT[2 * tid + 1];
    float f0 = sigmoidf_((v0.x - mu) * rs * gg0.x + bt0.x);
    float f1 = sigmoidf_((v0.y - mu) * rs * gg0.y + bt0.y);
    float f2 = sigmoidf_((v0.z - mu) * rs * gg0.z + bt0.z);
    float f3 = sigmoidf_((v0.w - mu) * rs * gg0.w + bt0.w);
    __half2* fd = g_fndh + (size_t)m * HH + 4 * tid;
    fd[0] = __floats2half2_rn(f0, (1.0f - f0) * __low2float(xt0));
    fd[1] = __floats2half2_rn(f1, (1.0f - f1) * __high2float(xt0));
    fd[2] = __floats2half2_rn(f2, (1.0f - f2) * __low2float(xt1));
    fd[3] = __floats2half2_rn(f3, (1.0f - f3) * __high2float(xt1));

    // r half: jg = 1024 + 4*tid ..
    float4 gg1 = ((const float4*)gg)[256 + tid];
    float4 bt1 = ((const float4*)betg)[256 + tid];
    __half2* rd = (__half2*)(g_rh + (size_t)m * HH + 4 * tid);
    rd[0] = __floats2half2_rn(sigmoidf_((v1.x - mu) * rs * gg1.x + bt1.x),
                              sigmoidf_((v1.y - mu) * rs * gg1.y + bt1.y));
    rd[1] = __floats2half2_rn(sigmoidf_((v1.z - mu) * rs * gg1.z + bt1.z),
                              sigmoidf_((v1.w - mu) * rs * gg1.w + bt1.w));
}

// ---------------- K3: sequential scan over T; explicit double-buffered prefetch ----------------
#define SCAN_U 8
__global__ __launch_bounds__(64)
void scan_kernel(const float* __restrict__ c0, float* __restrict__ cfinal) {
    const int ch = blockIdx.x * 64 + threadIdx.x;   // 0..16383
    const int b = ch >> 10, h = ch & 1023;
    float c = c0[ch];
    const __half2* src = g_fndh;                    // (f, nd) at (b*TT + t)*1024 + h
    float* dst = (float*)g_c4;
    const size_t base = (size_t)b * TT * 1024 + h;

    __half2 buf[SCAN_U];
    #pragma unroll
    for (int j = 0; j < SCAN_U; j++) buf[j] = src[base + (size_t)j * 1024];

    for (int t0 = 0; t0 < TT; t0 += SCAN_U) {
        __half2 cur[SCAN_U];
        #pragma unroll
        for (int j = 0; j < SCAN_U; j++) cur[j] = buf[j];
        if (t0 + SCAN_U < TT) {
            #pragma unroll
            for (int j = 0; j < SCAN_U; j++)
                buf[j] = src[base + (size_t)(t0 + SCAN_U + j) * 1024];
        }
        #pragma unroll
        for (int j = 0; j < SCAN_U; j++) {
            float2 v = __half22float2(cur[j]);
            c = fmaf(v.x, c, v.y);
            dst[base + (size_t)(t0 + j) * 1024] = c;
        }
    }
    cfinal[ch] = c;
}

// ---------------- K4: h = r * sigmoid(LN(all_c)) + (1-r) * x ----------------
__global__ __launch_bounds__(256)
void out_kernel(const float* __restrict__ x, const float* __restrict__ ga,
                const float* __restrict__ ba, float* __restrict__ hout) {
    __shared__ float sh[16];
    const int m = blockIdx.x;
    const int tid = threadIdx.x;

    float4 cv = g_c4[(size_t)m * 256 + tid];
    float s = cv.x + cv.y + cv.z + cv.w;
    float q = cv.x*cv.x + cv.y*cv.y + cv.z*cv.z + cv.w*cv.w;
    block_reduce2(s, q, sh);
    const float mu = s * (1.0f / 1024.0f);
    const float var = q * (1.0f / 1024.0f) - mu * mu;
    const float rs = rsqrtf(var + 1e-5f);

    float4 gv = ((const float4*)ga)[tid];
    float4 bv = ((const float4*)ba)[tid];
    const __half2* rp = (const __half2*)(g_rh + (size_t)m * HH + 4 * tid);
    float2 r01 = __half22float2(rp[0]);
    float2 r23 = __half22float2(rp[1]);
    float4 xv = ((const float4*)(x + (size_t)m * HH))[tid];
    float4 h;
    h.x = r01.x * sigmoidf_((cv.x - mu) * rs * gv.x + bv.x) + (1.0f - r01.x) * xv.x;
    h.y = r01.y * sigmoidf_((cv.y - mu) * rs * gv.y + bv.y) + (1.0f - r01.y) * xv.y;
    h.z = r23.x * sigmoidf_((cv.z - mu) * rs * gv.z + bv.z) + (1.0f - r23.x) * xv.z;
    h.w = r23.y * sigmoidf_((cv.w - mu) * rs * gv.w + bv.w) + (1.0f - r23.y) * xv.w;
    ((float4*)(hout + (size_t)m * HH))[tid] = h;
}

// ---------------- launch ----------------
extern "C" void kernel_launch(void* const* d_in, const int* in_sizes, int n_in,
                              void* d_out, int out_size) {
    const float* x    = (const float*)d_in[0];
    const float* c    = (const float*)d_in[1];
    const float* Wlt  = (const float*)d_in[2];
    const float* Wg   = (const float*)d_in[3];
    const float* bg   = (const float*)d_in[4];
    const float* gg   = (const float*)d_in[5];
    const float* betg = (const float*)d_in[6];
    const float* ga   = (const float*)d_in[7];
    const float* ba   = (const float*)d_in[8];
    float* out = (float*)d_out;

    __half* dXh; cudaGetSymbolAddress((void**)&dXh, g_Xh);
    __half* dWh; cudaGetSymbolAddress((void**)&dWh, g_Wh);

    // fp32 -> fp16 conversions
    cvt_kernel<<<(MM * DD / 4 + 255) / 256, 256>>>(x, dXh, MM * DD / 4);
    cvt_kernel<<<(HH * DD / 4 + 255) / 256, 256>>>(Wlt, dWh, HH * DD / 4);
    cvt_kernel<<<(2 * HH * DD / 4 + 255) / 256, 256>>>(Wg, dWh + (size_t)HH * DD,
                                                       2 * HH * DD / 4);

    cudaFuncSetAttribute(gemm_f16, cudaFuncAttributeMaxDynamicSharedMemorySize,
                         SMEM_GEMM_BYTES);
    dim3 grid(N3 / TNh, MM / TMh);   // (24, 256), x-major for L2 reuse of X strips
    gemm_f16<<<grid, 256, SMEM_GEMM_BYTES>>>();

    gate_kernel<<<MM, 256>>>(bg, gg, betg);
    scan_kernel<<<256, 64>>>(c, out + (size_t)MM * HH);
    out_kernel<<<MM, 256>>>(x, ga, ba, out);
}

// round 13
// speedup vs baseline: 1.0792x; 1.0320x over previous
#include <cuda_runtime.h>
#include <cuda_fp16.h>
#include <cstdint>

// Problem dims (fixed by the reference)
#define BB 16
#define TT 2048
#define DD 1024
#define HH 1024
#define MM (BB*TT)      // 32768 rows
#define N3 (3*HH)       // 3072 GEMM output cols: [x_tilde | g(2048)]

// ---------------- scratch (allocation-free __device__ globals) ----------------
__device__ __half  g_Xh[(size_t)MM * DD];       //  64 MB  fp16 X
__device__ __half  g_Wh[(size_t)N3 * DD];       //   6 MB  fp16 [Wlt; Wg]
__device__ __half  g_Yh[(size_t)MM * N3];       // 201 MB  GEMM output, fp16
__device__ __half2 g_fndh[(size_t)MM * HH];     // 134 MB  (f, nd) per (m,h), fp16
__device__ __half  g_rh[(size_t)MM * HH];       //  67 MB  r gate, fp16
__device__ __half  g_ch[(size_t)MM * HH];       //  67 MB  all_c, fp16

// ---------------- helpers ----------------
__device__ __forceinline__ uint32_t smem_u32(const void* p) {
    return (uint32_t)__cvta_generic_to_shared(p);
}
#define CP_ASYNC16(dst, src) \
    asm volatile("cp.async.cg.shared.global [%0], [%1], 16;" :: "r"(dst), "l"(src))
#define CP_COMMIT() asm volatile("cp.async.commit_group;" ::: "memory")

#define LDSM_X4(r0, r1, r2, r3, addr) \
    asm volatile("ldmatrix.sync.aligned.m8n8.x4.shared.b16 {%0,%1,%2,%3}, [%4];" \
        : "=r"(r0), "=r"(r1), "=r"(r2), "=r"(r3) : "r"(addr))

__device__ __forceinline__ void mma_f16(float* d, const uint32_t* a, const uint32_t* b) {
    asm volatile(
        "mma.sync.aligned.m16n8k16.row.col.f32.f16.f16.f32 "
        "{%0,%1,%2,%3}, {%4,%5,%6,%7}, {%8,%9}, {%0,%1,%2,%3};"
        : "+f"(d[0]), "+f"(d[1]), "+f"(d[2]), "+f"(d[3])
        : "r"(a[0]), "r"(a[1]), "r"(a[2]), "r"(a[3]),
          "r"(b[0]), "r"(b[1]));
}

__device__ __forceinline__ float sigmoidf_(float z) {
    return 1.0f / (1.0f + __expf(-z));
}

// block reduce (sum, sumsq) for 256-thread blocks (8 warps)
__device__ __forceinline__ void block_reduce2(float& s, float& q, float* sh) {
    #pragma unroll
    for (int o = 16; o; o >>= 1) {
        s += __shfl_xor_sync(0xFFFFFFFFu, s, o);
        q += __shfl_xor_sync(0xFFFFFFFFu, q, o);
    }
    int warp = threadIdx.x >> 5, lane = threadIdx.x & 31;
    if (lane == 0) { sh[warp] = s; sh[8 + warp] = q; }
    __syncthreads();
    if (threadIdx.x < 32) {
        float ss = (lane < 8) ? sh[lane] : 0.0f;
        float qq = (lane < 8) ? sh[8 + lane] : 0.0f;
        #pragma unroll
        for (int o = 4; o; o >>= 1) {
            ss += __shfl_xor_sync(0xFFFFFFFFu, ss, o);
            qq += __shfl_xor_sync(0xFFFFFFFFu, qq, o);
        }
        if (lane == 0) { sh[0] = ss; sh[8] = qq; }
    }
    __syncthreads();
    s = sh[0]; q = sh[8];
}

// ---------------- K0: fused fp32 -> fp16 conversion (X, Wlt, Wg in one grid) ----------------
#define X4N (MM * DD / 4)        // 8388608 float4s for X
#define WLT4N (HH * DD / 4)      // 262144
#define WG4N  (2 * HH * DD / 4)  // 524288
#define CVT_TOTAL (X4N + WLT4N + WG4N)

__global__ __launch_bounds__(256)
void cvt_all_kernel(const float* __restrict__ x, const float* __restrict__ wlt,
                    const float* __restrict__ wg) {
    int i = blockIdx.x * 256 + threadIdx.x;
    if (i >= CVT_TOTAL) return;
    const float* src;
    __half* dst;
    int j;
    if (i < X4N)                 { src = x;   dst = g_Xh;                       j = i; }
    else if (i < X4N + WLT4N)    { src = wlt; dst = g_Wh;                       j = i - X4N; }
    else                         { src = wg;  dst = g_Wh + (size_t)HH * DD;     j = i - X4N - WLT4N; }
    float4 v = ((const float4*)src)[j];
    __half2* d = (__half2*)dst;
    d[2 * j]     = __floats2half2_rn(v.x, v.y);
    d[2 * j + 1] = __floats2half2_rn(v.z, v.w);
}

// ---------------- K1: fp16 mma.sync GEMM  Y[m,n] = sum_d x[m,d] * W[n,d] ----------------
// CTA tile 128x128, warp tile 64x32 (8 warps as 2x4), K-chunk 64, 3-stage cp.async.
// ldmatrix.x4 fragment feeding; 2 CTAs/SM; one barrier per 64 HMMAs.  (R9 config, frozen)
#define TMh 128
#define TNh 128
#define KCh 64
#define LDKH 72                          // halfs per smem row (144B, conflict-free)
#define A_STH (TMh * LDKH)               // 9216 halfs
#define B_STH (TNh * LDKH)               // 9216 halfs
#define STAGE_H (A_STH + B_STH)          // 18432 halfs = 36864 B
#define SMEM_GEMM_BYTES (3 * STAGE_H * 2)   // 110592

// fill one stage with K-chunk kt: A 4 chunks/thread, B 4 chunks/thread (16B each)
__device__ __forceinline__ void load_stage(__half* stg, const __half* Xrow,
                                           const __half* Wrow, int kt, int tid) {
    const int kof = kt * KCh;
    const uint32_t aB = smem_u32(stg);
    const uint32_t bB = smem_u32(stg + A_STH);
    #pragma unroll
    for (int j = 0; j < 4; j++) {
        int c = tid + j * 256;           // 0..1023 = row*8 + q
        int row = c >> 3, q = c & 7;
        CP_ASYNC16(aB + (uint32_t)(row * 144 + q * 16),
                   Xrow + (size_t)row * DD + kof + q * 8);
    }
    #pragma unroll
    for (int j = 0; j < 4; j++) {
        int c = tid + j * 256;
        int row = c >> 3, q = c & 7;
        CP_ASYNC16(bB + (uint32_t)(row * 144 + q * 16),
                   Wrow + (size_t)row * DD + kof + q * 8);
    }
    CP_COMMIT();
}

__global__ __launch_bounds__(256, 2)
void gemm_f16(void) {
    extern __shared__ __half sh[];
    const int tid = threadIdx.x;
    const int lane = tid & 31, warp = tid >> 5;
    const int qr = lane >> 2, qc = lane & 3;
    const int wm = (warp >> 2) * 64, wn = (warp & 3) * 32;

    const int m_cta = blockIdx.y * TMh;
    const int n_cta = blockIdx.x * TNh;
    const __half* Xrow = g_Xh + (size_t)m_cta * DD;
    const __half* Wrow = g_Wh + (size_t)n_cta * DD;

    // ldmatrix byte offsets (relative to stage A / stage B bases)
    uint32_t aoff[4];
    {
        int row = lane & 15, col = (lane >> 4) * 8;
        #pragma unroll
        for (int mi = 0; mi < 4; mi++)
            aoff[mi] = (uint32_t)(((wm + mi * 16 + row) * LDKH + col) * 2);
    }
    uint32_t boff[2];
    {
        int subm = lane >> 3, within = lane & 7;
        int rb = (subm >> 1) * 8 + within, cb = (subm & 1) * 8;
        #pragma unroll
        for (int p = 0; p < 2; p++)
            boff[p] = (uint32_t)(((wn + p * 16 + rb) * LDKH + cb) * 2);
    }
    const uint32_t smem_base = smem_u32(sh);

    float acc[4][4][4];
    #pragma unroll
    for (int mi = 0; mi < 4; mi++)
        #pragma unroll
        for (int ni = 0; ni < 4; ni++)
            #pragma unroll
            for (int k = 0; k < 4; k++) acc[mi][ni][k] = 0.0f;

    // prologue: stages 0,1 <- chunks 0,1
    load_stage(sh, Xrow, Wrow, 0, tid);
    load_stage(sh + STAGE_H, Xrow, Wrow, 1, tid);

    const int KT = DD / KCh;   // 16
    int stage = 0;
    for (int kt = 0; kt < KT; kt++) {
        if (kt < 15) { asm volatile("cp.async.wait_group 1;" ::: "memory"); }
        else         { asm volatile("cp.async.wait_group 0;" ::: "memory"); }
        __syncthreads();   // chunk kt visible; everyone done computing kt-1

        if (kt + 2 < KT) {
            int ps = stage + 2; if (ps >= 3) ps -= 3;
            load_stage(sh + ps * STAGE_H, Xrow, Wrow, kt + 2, tid);
        }

        const uint32_t stA = smem_base + (uint32_t)(stage * STAGE_H * 2);
        const uint32_t stB = stA + A_STH * 2;

        #pragma unroll
        for (int kk = 0; kk < 4; kk++) {
            uint32_t a[4][4], b[4][2];
            #pragma unroll
            for (int mi = 0; mi < 4; mi++)
                LDSM_X4(a[mi][0], a[mi][1], a[mi][2], a[mi][3],
                        stA + aoff[mi] + kk * 32);
            #pragma unroll
            for (int p = 0; p < 2; p++)
                LDSM_X4(b[2*p][0], b[2*p][1], b[2*p+1][0], b[2*p+1][1],
                        stB + boff[p] + kk * 32);
            #pragma unroll
            for (int mi = 0; mi < 4; mi++)
                #pragma unroll
                for (int ni = 0; ni < 4; ni++)
                    mma_f16(acc[mi][ni], a[mi], b[ni]);
        }
        if (++stage == 3) stage = 0;
    }

    // epilogue: fp16 stores (rows qr / qr+8, cols 2qc,2qc+1)
    __half* Y = g_Yh;
    #pragma unroll
    for (int mi = 0; mi < 4; mi++) {
        #pragma unroll
        for (int ni = 0; ni < 4; ni++) {
            int r = m_cta + wm + mi * 16 + qr;
            int col = n_cta + wn + ni * 8 + qc * 2;
            *(__half2*)&Y[(size_t)r * N3 + col] =
                __floats2half2_rn(acc[mi][ni][0], acc[mi][ni][1]);
            *(__half2*)&Y[(size_t)(r + 8) * N3 + col] =
                __floats2half2_rn(acc[mi][ni][2], acc[mi][ni][3]);
        }
    }
}

// ---------------- K2: gate = sigmoid(LN(g + b_g)); emit (f,nd) half2 and r half ----------------
__global__ __launch_bounds__(256)
void gate_kernel(const float* __restrict__ bg, const float* __restrict__ gg,
                 const float* __restrict__ betg) {
    __shared__ float sh[16];
    const int m = blockIdx.x;
    const int tid = threadIdx.x;
    const __half* Yrow = g_Yh + (size_t)m * N3;

    // g half: 8 values per thread (4*tid..4*tid+3 and +1024)
    const __half2* G = (const __half2*)(Yrow + HH);
    __half2 ga0 = G[2 * tid], ga1 = G[2 * tid + 1];
    __half2 gb0 = G[512 + 2 * tid], gb1 = G[512 + 2 * tid + 1];
    float4 b0 = ((const float4*)bg)[tid];
    float4 b1 = ((const float4*)bg)[256 + tid];
    float4 v0, v1;
    v0.x = __low2float(ga0) + b0.x;  v0.y = __high2float(ga0) + b0.y;
    v0.z = __low2float(ga1) + b0.z;  v0.w = __high2float(ga1) + b0.w;
    v1.x = __low2float(gb0) + b1.x;  v1.y = __high2float(gb0) + b1.y;
    v1.z = __low2float(gb1) + b1.z;  v1.w = __high2float(gb1) + b1.w;

    float s = v0.x + v0.y + v0.z + v0.w + v1.x + v1.y + v1.z + v1.w;
    float q = v0.x*v0.x + v0.y*v0.y + v0.z*v0.z + v0.w*v0.w
            + v1.x*v1.x + v1.y*v1.y + v1.z*v1.z + v1.w*v1.w;
    block_reduce2(s, q, sh);
    const float mu = s * (1.0f / 2048.0f);
    const float var = q * (1.0f / 2048.0f) - mu * mu;
    const float rs = rsqrtf(var + 1e-5f);

    // f half: j = 4*tid .. 4*tid+3
    float4 gg0 = ((const float4*)gg)[tid];
    float4 bt0 = ((const float4*)betg)[tid];
    const __half2* XT = (const __half2*)Yrow;
    __half2 xt0 = XT[2 * tid], xt1 = XT[2 * tid + 1];
    float f0 = sigmoidf_((v0.x - mu) * rs * gg0.x + bt0.x);
    float f1 = sigmoidf_((v0.y - mu) * rs * gg0.y + bt0.y);
    float f2 = sigmoidf_((v0.z - mu) * rs * gg0.z + bt0.z);
    float f3 = sigmoidf_((v0.w - mu) * rs * gg0.w + bt0.w);
    __half2* fd = g_fndh + (size_t)m * HH + 4 * tid;
    fd[0] = __floats2half2_rn(f0, (1.0f - f0) * __low2float(xt0));
    fd[1] = __floats2half2_rn(f1, (1.0f - f1) * __high2float(xt0));
    fd[2] = __floats2half2_rn(f2, (1.0f - f2) * __low2float(xt1));
    fd[3] = __floats2half2_rn(f3, (1.0f - f3) * __high2float(xt1));

    // r half: jg = 1024 + 4*tid ..
    float4 gg1 = ((const float4*)gg)[256 + tid];
    float4 bt1 = ((const float4*)betg)[256 + tid];
    __half2* rd = (__half2*)(g_rh + (size_t)m * HH + 4 * tid);
    rd[0] = __floats2half2_rn(sigmoidf_((v1.x - mu) * rs * gg1.x + bt1.x),
                              sigmoidf_((v1.y - mu) * rs * gg1.y + bt1.y));
    rd[1] = __floats2half2_rn(sigmoidf_((v1.z - mu) * rs * gg1.z + bt1.z),
                              sigmoidf_((v1.w - mu) * rs * gg1.w + bt1.w));
}

// ---------------- K3: sequential scan over T; explicit double-buffered prefetch ----------------
#define SCAN_U 8
__global__ __launch_bounds__(64)
void scan_kernel(const float* __restrict__ c0, float* __restrict__ cfinal) {
    const int ch = blockIdx.x * 64 + threadIdx.x;   // 0..16383
    const int b = ch >> 10, h = ch & 1023;
    float c = c0[ch];
    const __half2* src = g_fndh;                    // (f, nd) at (b*TT + t)*1024 + h
    __half* dst = g_ch;
    const size_t base = (size_t)b * TT * 1024 + h;

    __half2 buf[SCAN_U];
    #pragma unroll
    for (int j = 0; j < SCAN_U; j++) buf[j] = src[base + (size_t)j * 1024];

    for (int t0 = 0; t0 < TT; t0 += SCAN_U) {
        __half2 cur[SCAN_U];
        #pragma unroll
        for (int j = 0; j < SCAN_U; j++) cur[j] = buf[j];
        if (t0 + SCAN_U < TT) {
            #pragma unroll
            for (int j = 0; j < SCAN_U; j++)
                buf[j] = src[base + (size_t)(t0 + SCAN_U + j) * 1024];
        }
        #pragma unroll
        for (int j = 0; j < SCAN_U; j++) {
            float2 v = __half22float2(cur[j]);
            c = fmaf(v.x, c, v.y);
            dst[base + (size_t)(t0 + j) * 1024] = __float2half_rn(c);
        }
    }
    cfinal[ch] = c;
}

// ---------------- K4: h = r * sigmoid(LN(all_c)) + (1-r) * x ----------------
__global__ __launch_bounds__(256)
void out_kernel(const float* __restrict__ ga, const float* __restrict__ ba,
                float* __restrict__ hout) {
    __shared__ float sh[16];
    const int m = blockIdx.x;
    const int tid = threadIdx.x;

    const __half2* cp = (const __half2*)(g_ch + (size_t)m * HH + 4 * tid);
    float2 c01 = __half22float2(cp[0]);
    float2 c23 = __half22float2(cp[1]);
    float s = c01.x + c01.y + c23.x + c23.y;
    float q = c01.x*c01.x + c01.y*c01.y + c23.x*c23.x + c23.y*c23.y;
    block_reduce2(s, q, sh);
    const float mu = s * (1.0f / 1024.0f);
    const float var = q * (1.0f / 1024.0f) - mu * mu;
    const float rs = rsqrtf(var + 1e-5f);

    float4 gv = ((const float4*)ga)[tid];
    float4 bv = ((const float4*)ba)[tid];
    const __half2* rp = (const __half2*)(g_rh + (size_t)m * HH + 4 * tid);
    float2 r01 = __half22float2(rp[0]);
    float2 r23 = __half22float2(rp[1]);
    const __half2* xp = (const __half2*)(g_Xh + (size_t)m * HH + 4 * tid);
    float2 x01 = __half22float2(xp[0]);
    float2 x23 = __half22float2(xp[1]);
    float4 h;
    h.x = r01.x * sigmoidf_((c01.x - mu) * rs * gv.x + bv.x) + (1.0f - r01.x) * x01.x;
    h.y = r01.y * sigmoidf_((c01.y - mu) * rs * gv.y + bv.y) + (1.0f - r01.y) * x01.y;
    h.z = r23.x * sigmoidf_((c23.x - mu) * rs * gv.z + bv.z) + (1.0f - r23.x) * x23.x;
    h.w = r23.y * sigmoidf_((c23.y - mu) * rs * gv.w + bv.w) + (1.0f - r23.y) * x23.y;
    ((float4*)(hout + (size_t)m * HH))[tid] = h;
}

// ---------------- launch ----------------
extern "C" void kernel_launch(void* const* d_in, const int* in_sizes, int n_in,
                              void* d_out, int out_size) {
    const float* x    = (const float*)d_in[0];
    const float* c    = (const float*)d_in[1];
    const float* Wlt  = (const float*)d_in[2];
    const float* Wg   = (const float*)d_in[3];
    const float* bg   = (const float*)d_in[4];
    const float* gg   = (const float*)d_in[5];
    const float* betg = (const float*)d_in[6];
    const float* ga   = (const float*)d_in[7];
    const float* ba   = (const float*)d_in[8];
    float* out = (float*)d_out;

    // fused fp32 -> fp16 conversion (X, Wlt, Wg)
    cvt_all_kernel<<<(CVT_TOTAL + 255) / 256, 256>>>(x, Wlt, Wg);

    cudaFuncSetAttribute(gemm_f16, cudaFuncAttributeMaxDynamicSharedMemorySize,
                         SMEM_GEMM_BYTES);
    dim3 grid(N3 / TNh, MM / TMh);   // (24, 256), x-major for L2 reuse of X strips
    gemm_f16<<<grid, 256, SMEM_GEMM_BYTES>>>();

    gate_kernel<<<MM, 256>>>(bg, gg, betg);
    scan_kernel<<<256, 64>>>(c, out + (size_t)MM * HH);
    out_kernel<<<MM, 256>>>(ga, ba, out);
}

// round 15
// speedup vs baseline: 1.2166x; 1.1273x over previous
#include <cuda_runtime.h>
#include <cuda_fp16.h>
#include <cstdint>

// Problem dims (fixed by the reference)
#define BB 16
#define TT 2048
#define DD 1024
#define HH 1024
#define MM (BB*TT)      // 32768 rows
#define N3 (3*HH)       // 3072 GEMM output cols: [x_tilde | g(2048)]
#define NCH (BB*HH)     // 16384 scan channels
#define NSEG 8
#define SEGT (TT/NSEG)  // 256 timesteps per segment

// ---------------- scratch (allocation-free __device__ globals) ----------------
__device__ __half  g_Xh[(size_t)MM * DD];       //  64 MB  fp16 X
__device__ __half  g_Wh[(size_t)N3 * DD];       //   6 MB  fp16 [Wlt; Wg]
__device__ __half  g_Yh[(size_t)MM * N3];       // 201 MB  GEMM output, fp16
__device__ __half2 g_fndh[(size_t)MM * HH];     // 134 MB  (f, nd) per (m,h), fp16
__device__ __half  g_rh[(size_t)MM * HH];       //  67 MB  r gate, fp16
__device__ __half  g_ch[(size_t)MM * HH];       //  67 MB  all_c, fp16
__device__ float   g_P[NCH * NSEG];             // segment f-products
__device__ float   g_Bv[NCH * NSEG];            // segment zero-init scan results
__device__ float   g_cinit[NCH * NSEG];         // segment initial states

// ---------------- helpers ----------------
__device__ __forceinline__ uint32_t smem_u32(const void* p) {
    return (uint32_t)__cvta_generic_to_shared(p);
}
#define CP_ASYNC16(dst, src) \
    asm volatile("cp.async.cg.shared.global [%0], [%1], 16;" :: "r"(dst), "l"(src))
#define CP_COMMIT() asm volatile("cp.async.commit_group;" ::: "memory")

#define LDSM_X4(r0, r1, r2, r3, addr) \
    asm volatile("ldmatrix.sync.aligned.m8n8.x4.shared.b16 {%0,%1,%2,%3}, [%4];" \
        : "=r"(r0), "=r"(r1), "=r"(r2), "=r"(r3) : "r"(addr))

__device__ __forceinline__ void mma_f16(float* d, const uint32_t* a, const uint32_t* b) {
    asm volatile(
        "mma.sync.aligned.m16n8k16.row.col.f32.f16.f16.f32 "
        "{%0,%1,%2,%3}, {%4,%5,%6,%7}, {%8,%9}, {%0,%1,%2,%3};"
        : "+f"(d[0]), "+f"(d[1]), "+f"(d[2]), "+f"(d[3])
        : "r"(a[0]), "r"(a[1]), "r"(a[2]), "r"(a[3]),
          "r"(b[0]), "r"(b[1]));
}

__device__ __forceinline__ float sigmoidf_(float z) {
    return 1.0f / (1.0f + __expf(-z));
}

// block reduce (sum, sumsq) for 256-thread blocks (8 warps)
__device__ __forceinline__ void block_reduce2(float& s, float& q, float* sh) {
    #pragma unroll
    for (int o = 16; o; o >>= 1) {
        s += __shfl_xor_sync(0xFFFFFFFFu, s, o);
        q += __shfl_xor_sync(0xFFFFFFFFu, q, o);
    }
    int warp = threadIdx.x >> 5, lane = threadIdx.x & 31;
    if (lane == 0) { sh[warp] = s; sh[8 + warp] = q; }
    __syncthreads();
    if (threadIdx.x < 32) {
        float ss = (lane < 8) ? sh[lane] : 0.0f;
        float qq = (lane < 8) ? sh[8 + lane] : 0.0f;
        #pragma unroll
        for (int o = 4; o; o >>= 1) {
            ss += __shfl_xor_sync(0xFFFFFFFFu, ss, o);
            qq += __shfl_xor_sync(0xFFFFFFFFu, qq, o);
        }
        if (lane == 0) { sh[0] = ss; sh[8] = qq; }
    }
    __syncthreads();
    s = sh[0]; q = sh[8];
}

// ---------------- K0: fused fp32 -> fp16 conversion (X, Wlt, Wg in one grid) ----------------
#define X4N (MM * DD / 4)
#define WLT4N (HH * DD / 4)
#define WG4N  (2 * HH * DD / 4)
#define CVT_TOTAL (X4N + WLT4N + WG4N)

__global__ __launch_bounds__(256)
void cvt_all_kernel(const float* __restrict__ x, const float* __restrict__ wlt,
                    const float* __restrict__ wg) {
    int i = blockIdx.x * 256 + threadIdx.x;
    if (i >= CVT_TOTAL) return;
    const float* src;
    __half* dst;
    int j;
    if (i < X4N)                 { src = x;   dst = g_Xh;                   j = i; }
    else if (i < X4N + WLT4N)    { src = wlt; dst = g_Wh;                   j = i - X4N; }
    else                         { src = wg;  dst = g_Wh + (size_t)HH * DD; j = i - X4N - WLT4N; }
    float4 v = ((const float4*)src)[j];
    __half2* d = (__half2*)dst;
    d[2 * j]     = __floats2half2_rn(v.x, v.y);
    d[2 * j + 1] = __floats2half2_rn(v.z, v.w);
}

// ---------------- K1: fp16 mma.sync GEMM  (R9 config, frozen) ----------------
#define TMh 128
#define TNh 128
#define KCh 64
#define LDKH 72
#define A_STH (TMh * LDKH)
#define B_STH (TNh * LDKH)
#define STAGE_H (A_STH + B_STH)
#define SMEM_GEMM_BYTES (3 * STAGE_H * 2)   // 110592

__device__ __forceinline__ void load_stage(__half* stg, const __half* Xrow,
                                           const __half* Wrow, int kt, int tid) {
    const int kof = kt * KCh;
    const uint32_t aB = smem_u32(stg);
    const uint32_t bB = smem_u32(stg + A_STH);
    #pragma unroll
    for (int j = 0; j < 4; j++) {
        int c = tid + j * 256;
        int row = c >> 3, q = c & 7;
        CP_ASYNC16(aB + (uint32_t)(row * 144 + q * 16),
                   Xrow + (size_t)row * DD + kof + q * 8);
    }
    #pragma unroll
    for (int j = 0; j < 4; j++) {
        int c = tid + j * 256;
        int row = c >> 3, q = c & 7;
        CP_ASYNC16(bB + (uint32_t)(row * 144 + q * 16),
                   Wrow + (size_t)row * DD + kof + q * 8);
    }
    CP_COMMIT();
}

__global__ __launch_bounds__(256, 2)
void gemm_f16(void) {
    extern __shared__ __half sh[];
    const int tid = threadIdx.x;
    const int lane = tid & 31, warp = tid >> 5;
    const int qr = lane >> 2, qc = lane & 3;
    const int wm = (warp >> 2) * 64, wn = (warp & 3) * 32;

    const int m_cta = blockIdx.y * TMh;
    const int n_cta = blockIdx.x * TNh;
    const __half* Xrow = g_Xh + (size_t)m_cta * DD;
    const __half* Wrow = g_Wh + (size_t)n_cta * DD;

    uint32_t aoff[4];
    {
        int row = lane & 15, col = (lane >> 4) * 8;
        #pragma unroll
        for (int mi = 0; mi < 4; mi++)
            aoff[mi] = (uint32_t)(((wm + mi * 16 + row) * LDKH + col) * 2);
    }
    uint32_t boff[2];
    {
        int subm = lane >> 3, within = lane & 7;
        int rb = (subm >> 1) * 8 + within, cb = (subm & 1) * 8;
        #pragma unroll
        for (int p = 0; p < 2; p++)
            boff[p] = (uint32_t)(((wn + p * 16 + rb) * LDKH + cb) * 2);
    }
    const uint32_t smem_base = smem_u32(sh);

    float acc[4][4][4];
    #pragma unroll
    for (int mi = 0; mi < 4; mi++)
        #pragma unroll
        for (int ni = 0; ni < 4; ni++)
            #pragma unroll
            for (int k = 0; k < 4; k++) acc[mi][ni][k] = 0.0f;

    load_stage(sh, Xrow, Wrow, 0, tid);
    load_stage(sh + STAGE_H, Xrow, Wrow, 1, tid);

    const int KT = DD / KCh;   // 16
    int stage = 0;
    for (int kt = 0; kt < KT; kt++) {
        if (kt < 15) { asm volatile("cp.async.wait_group 1;" ::: "memory"); }
        else         { asm volatile("cp.async.wait_group 0;" ::: "memory"); }
        __syncthreads();

        if (kt + 2 < KT) {
            int ps = stage + 2; if (ps >= 3) ps -= 3;
            load_stage(sh + ps * STAGE_H, Xrow, Wrow, kt + 2, tid);
        }

        const uint32_t stA = smem_base + (uint32_t)(stage * STAGE_H * 2);
        const uint32_t stB = stA + A_STH * 2;

        #pragma unroll
        for (int kk = 0; kk < 4; kk++) {
            uint32_t a[4][4], b[4][2];
            #pragma unroll
            for (int mi = 0; mi < 4; mi++)
                LDSM_X4(a[mi][0], a[mi][1], a[mi][2], a[mi][3],
                        stA + aoff[mi] + kk * 32);
            #pragma unroll
            for (int p = 0; p < 2; p++)
                LDSM_X4(b[2*p][0], b[2*p][1], b[2*p+1][0], b[2*p+1][1],
                        stB + boff[p] + kk * 32);
            #pragma unroll
            for (int mi = 0; mi < 4; mi++)
                #pragma unroll
                for (int ni = 0; ni < 4; ni++)
                    mma_f16(acc[mi][ni], a[mi], b[ni]);
        }
        if (++stage == 3) stage = 0;
    }

    __half* Y = g_Yh;
    #pragma unroll
    for (int mi = 0; mi < 4; mi++) {
        #pragma unroll
        for (int ni = 0; ni < 4; ni++) {
            int r = m_cta + wm + mi * 16 + qr;
            int col = n_cta + wn + ni * 8 + qc * 2;
            *(__half2*)&Y[(size_t)r * N3 + col] =
                __floats2half2_rn(acc[mi][ni][0], acc[mi][ni][1]);
            *(__half2*)&Y[(size_t)(r + 8) * N3 + col] =
                __floats2half2_rn(acc[mi][ni][2], acc[mi][ni][3]);
        }
    }
}

// ---------------- K2: gate = sigmoid(LN(g + b_g)); emit (f,nd) half2 and r half ----------------
__global__ __launch_bounds__(256)
void gate_kernel(const float* __restrict__ bg, const float* __restrict__ gg,
                 const float* __restrict__ betg) {
    __shared__ float sh[16];
    const int m = blockIdx.x;
    const int tid = threadIdx.x;
    const __half* Yrow = g_Yh + (size_t)m * N3;

    const __half2* G = (const __half2*)(Yrow + HH);
    __half2 ga0 = G[2 * tid], ga1 = G[2 * tid + 1];
    __half2 gb0 = G[512 + 2 * tid], gb1 = G[512 + 2 * tid + 1];
    float4 b0 = ((const float4*)bg)[tid];
    float4 b1 = ((const float4*)bg)[256 + tid];
    float4 v0, v1;
    v0.x = __low2float(ga0) + b0.x;  v0.y = __high2float(ga0) + b0.y;
    v0.z = __low2float(ga1) + b0.z;  v0.w = __high2float(ga1) + b0.w;
    v1.x = __low2float(gb0) + b1.x;  v1.y = __high2float(gb0) + b1.y;
    v1.z = __low2float(gb1) + b1.z;  v1.w = __high2float(gb1) + b1.w;

    float s = v0.x + v0.y + v0.z + v0.w + v1.x + v1.y + v1.z + v1.w;
    float q = v0.x*v0.x + v0.y*v0.y + v0.z*v0.z + v0.w*v0.w
            + v1.x*v1.x + v1.y*v1.y + v1.z*v1.z + v1.w*v1.w;
    block_reduce2(s, q, sh);
    const float mu = s * (1.0f / 2048.0f);
    const float var = q * (1.0f / 2048.0f) - mu * mu;
    const float rs = rsqrtf(var + 1e-5f);

    float4 gg0 = ((const float4*)gg)[tid];
    float4 bt0 = ((const float4*)betg)[tid];
    const __half2* XT = (const __half2*)Yrow;
    __half2 xt0 = XT[2 * tid], xt1 = XT[2 * tid + 1];
    float f0 = sigmoidf_((v0.x - mu) * rs * gg0.x + bt0.x);
    float f1 = sigmoidf_((v0.y - mu) * rs * gg0.y + bt0.y);
    float f2 = sigmoidf_((v0.z - mu) * rs * gg0.z + bt0.z);
    float f3 = sigmoidf_((v0.w - mu) * rs * gg0.w + bt0.w);
    __half2* fd = g_fndh + (size_t)m * HH + 4 * tid;
    fd[0] = __floats2half2_rn(f0, (1.0f - f0) * __low2float(xt0));
    fd[1] = __floats2half2_rn(f1, (1.0f - f1) * __high2float(xt0));
    fd[2] = __floats2half2_rn(f2, (1.0f - f2) * __low2float(xt1));
    fd[3] = __floats2half2_rn(f3, (1.0f - f3) * __high2float(xt1));

    float4 gg1 = ((const float4*)gg)[256 + tid];
    float4 bt1 = ((const float4*)betg)[256 + tid];
    __half2* rd = (__half2*)(g_rh + (size_t)m * HH + 4 * tid);
    rd[0] = __floats2half2_rn(sigmoidf_((v1.x - mu) * rs * gg1.x + bt1.x),
                              sigmoidf_((v1.y - mu) * rs * gg1.y + bt1.y));
    rd[1] = __floats2half2_rn(sigmoidf_((v1.z - mu) * rs * gg1.z + bt1.z),
                              sigmoidf_((v1.w - mu) * rs * gg1.w + bt1.w));
}

// ---------------- K3a: per-segment (P, B) ----------------
#define SCAN_U 8
__global__ __launch_bounds__(256)
void scan_partA(void) {
    const int tid = blockIdx.x * 256 + threadIdx.x;   // 0..NCH*NSEG-1
    const int s = tid >> 14;                           // segment 0..7
    const int ch = tid & (NCH - 1);
    const int b = ch >> 10, h = ch & 1023;
    const size_t base = ((size_t)b * TT + (size_t)s * SEGT) * 1024 + h;

    float c = 0.0f, P = 1.0f;
    __half2 buf[SCAN_U];
    #pragma unroll
    for (int j = 0; j < SCAN_U; j++) buf[j] = g_fndh[base + (size_t)j * 1024];

    for (int t0 = 0; t0 < SEGT; t0 += SCAN_U) {
        __half2 cur[SCAN_U];
        #pragma unroll
        for (int j = 0; j < SCAN_U; j++) cur[j] = buf[j];
        if (t0 + SCAN_U < SEGT) {
            #pragma unroll
            for (int j = 0; j < SCAN_U; j++)
                buf[j] = g_fndh[base + (size_t)(t0 + SCAN_U + j) * 1024];
        }
        #pragma unroll
        for (int j = 0; j < SCAN_U; j++) {
            float2 v = __half22float2(cur[j]);
            c = fmaf(v.x, c, v.y);
            P *= v.x;
        }
    }
    g_P[s * NCH + ch]  = P;
    g_Bv[s * NCH + ch] = c;
}

// ---------------- K3b: combine segments; emit cinit per segment + c_final ----------------
__global__ __launch_bounds__(256)
void scan_partB(const float* __restrict__ c0, float* __restrict__ cfinal) {
    const int ch = blockIdx.x * 256 + threadIdx.x;    // 0..NCH-1
    float c = c0[ch];
    #pragma unroll
    for (int s = 0; s < NSEG; s++) {
        g_cinit[s * NCH + ch] = c;
        c = fmaf(g_P[s * NCH + ch], c, g_Bv[s * NCH + ch]);
    }
    cfinal[ch] = c;
}

// ---------------- K3c: re-scan each segment from true cinit; write all_c ----------------
__global__ __launch_bounds__(256)
void scan_partC(void) {
    const int tid = blockIdx.x * 256 + threadIdx.x;
    const int s = tid >> 14;
    const int ch = tid & (NCH - 1);
    const int b = ch >> 10, h = ch & 1023;
    const size_t base = ((size_t)b * TT + (size_t)s * SEGT) * 1024 + h;

    float c = g_cinit[s * NCH + ch];
    __half2 buf[SCAN_U];
    #pragma unroll
    for (int j = 0; j < SCAN_U; j++) buf[j] = g_fndh[base + (size_t)j * 1024];

    for (int t0 = 0; t0 < SEGT; t0 += SCAN_U) {
        __half2 cur[SCAN_U];
        #pragma unroll
        for (int j = 0; j < SCAN_U; j++) cur[j] = buf[j];
        if (t0 + SCAN_U < SEGT) {
            #pragma unroll
            for (int j = 0; j < SCAN_U; j++)
                buf[j] = g_fndh[base + (size_t)(t0 + SCAN_U + j) * 1024];
        }
        #pragma unroll
        for (int j = 0; j < SCAN_U; j++) {
            float2 v = __half22float2(cur[j]);
            c = fmaf(v.x, c, v.y);
            g_ch[base + (size_t)(t0 + j) * 1024] = __float2half_rn(c);
        }
    }
}

// ---------------- K4: h = r * sigmoid(LN(all_c)) + (1-r) * x ----------------
__global__ __launch_bounds__(256)
void out_kernel(const float* __restrict__ ga, const float* __restrict__ ba,
                float* __restrict__ hout) {
    __shared__ float sh[16];
    const int m = blockIdx.x;
    const int tid = threadIdx.x;

    const __half2* cp = (const __half2*)(g_ch + (size_t)m * HH + 4 * tid);
    float2 c01 = __half22float2(cp[0]);
    float2 c23 = __half22float2(cp[1]);
    float s = c01.x + c01.y + c23.x + c23.y;
    float q = c01.x*c01.x + c01.y*c01.y + c23.x*c23.x + c23.y*c23.y;
    block_reduce2(s, q, sh);
    const float mu = s * (1.0f / 1024.0f);
    const float var = q * (1.0f / 1024.0f) - mu * mu;
    const float rs = rsqrtf(var + 1e-5f);

    float4 gv = ((const float4*)ga)[tid];
    float4 bv = ((const float4*)ba)[tid];
    const __half2* rp = (const __half2*)(g_rh + (size_t)m * HH + 4 * tid);
    float2 r01 = __half22float2(rp[0]);
    float2 r23 = __half22float2(rp[1]);
    const __half2* xp = (const __half2*)(g_Xh + (size_t)m * HH + 4 * tid);
    float2 x01 = __half22float2(xp[0]);
    float2 x23 = __half22float2(xp[1]);
    float4 h;
    h.x = r01.x * sigmoidf_((c01.x - mu) * rs * gv.x + bv.x) + (1.0f - r01.x) * x01.x;
    h.y = r01.y * sigmoidf_((c01.y - mu) * rs * gv.y + bv.y) + (1.0f - r01.y) * x01.y;
    h.z = r23.x * sigmoidf_((c23.x - mu) * rs * gv.z + bv.z) + (1.0f - r23.x) * x23.x;
    h.w = r23.y * sigmoidf_((c23.y - mu) * rs * gv.w + bv.w) + (1.0f - r23.y) * x23.y;
    ((float4*)(hout + (size_t)m * HH))[tid] = h;
}

// ---------------- launch ----------------
extern "C" void kernel_launch(void* const* d_in, const int* in_sizes, int n_in,
                              void* d_out, int out_size) {
    const float* x    = (const float*)d_in[0];
    const float* c    = (const float*)d_in[1];
    const float* Wlt  = (const float*)d_in[2];
    const float* Wg   = (const float*)d_in[3];
    const float* bg   = (const float*)d_in[4];
    const float* gg   = (const float*)d_in[5];
    const float* betg = (const float*)d_in[6];
    const float* ga   = (const float*)d_in[7];
    const float* ba   = (const float*)d_in[8];
    float* out = (float*)d_out;

    cvt_all_kernel<<<(CVT_TOTAL + 255) / 256, 256>>>(x, Wlt, Wg);

    cudaFuncSetAttribute(gemm_f16, cudaFuncAttributeMaxDynamicSharedMemorySize,
                         SMEM_GEMM_BYTES);
    dim3 grid(N3 / TNh, MM / TMh);   // (24, 256)
    gemm_f16<<<grid, 256, SMEM_GEMM_BYTES>>>();

    gate_kernel<<<MM, 256>>>(bg, gg, betg);
    scan_partA<<<NCH * NSEG / 256, 256>>>();
    scan_partB<<<NCH / 256, 256>>>(c, out + (size_t)MM * HH);
    scan_partC<<<NCH * NSEG / 256, 256>>>();
    out_kernel<<<MM, 256>>>(ga, ba, out);
}